// round 14
// baseline (speedup 1.0000x reference)
#include <cuda_runtime.h>
#include <cuda_bf16.h>

// Problem constants (must match reference)
#define NUM_NODES   1200000
#define NUM_PHYS    1000000
#define NUM_MOVABLE 900000
#define NB          512
#define KSTEN       5

// BSX = BSY = 1000/512 = 1.953125 (exact in fp32)
#define BS 1.953125f

// Compile-time double folds, cast to f32 exactly as JAX weak-type promotion does
__device__ __forceinline__ float stretch_c() { return (float)(1.953125 * 1.4142135623730951); }
__device__ __forceinline__ float cap_denom() { return (float)(1.953125 * 1.953125 * 0.05); }
__device__ __forceinline__ float min_rate()  { return (float)(1.0 / 1.5); }

// Scratch (no allocations allowed). Row-major bin maps, 16B-aligned.
// __device__ globals are zero-init at load; k_util re-zeroes g_pin_map every
// run, so "pin_map == 0 at scatter entry" holds for the correctness call,
// the capture call, and every graph replay.
__device__ __align__(16) float g_pin_map[NB * NB];
__device__ __align__(16) float g_util[NB * NB];

__device__ __forceinline__ void red_add_v2(float* addr, float x, float y) {
    asm volatile("red.global.add.v2.f32 [%0], {%1, %2};"
                 :: "l"(addr), "f"(x), "f"(y) : "memory");
}
__device__ __forceinline__ void red_add_v4(float* addr, float a, float b, float c, float d) {
    asm volatile("red.global.add.v4.f32 [%0], {%1, %2, %3, %4};"
                 :: "l"(addr), "f"(a), "f"(b), "f"(c), "f"(d) : "memory");
}

// ---------------------------------------------------------------------------
// Overlap stencil — matches reference _overlap_terms exactly:
//   il = clip(floor(lo/BS), 0, NB-1); idx = il + k; valid = idx < NB;
//   idx = min(idx, NB-1); b_lo = idx*BS;
//   ov = max(min(hi, b_lo+BS) - max(lo, b_lo), 0); 0 where invalid.
// True division lo/BS so floor matches JAX bit-for-bit at bin boundaries.
// ---------------------------------------------------------------------------
__device__ __forceinline__ void overlap_terms(float lo, float hi,
                                              int idx[KSTEN], float ov[KSTEN]) {
    int il = (int)floorf(lo / BS);
    il = min(max(il, 0), NB - 1);
#pragma unroll
    for (int k = 0; k < KSTEN; k++) {
        int id = il + k;
        bool valid = id < NB;
        id = min(id, NB - 1);
        float b_lo = (float)id * BS;              // exact: id*125/64 fits in 24 bits
        float o = fminf(hi, b_lo + BS) - fmaxf(lo, b_lo);
        o = fmaxf(o, 0.0f);
        idx[k] = id;
        ov[k]  = valid ? o : 0.0f;
    }
}

// Pack the y-stencil (span <= 3 taps) into a 2-aligned 4-slot window.
// Returns window start a; fills v[0..3]; need1 = slots 2/3 occupied.
__device__ __forceinline__ int pack_y(const int iy[KSTEN], const float ovy[KSTEN],
                                      float scale, float v[4], bool& need1) {
    int j0 = iy[0];
    int s  = j0 & 1;
    int a  = j0 - s;
    v[0] = v[1] = v[2] = v[3] = 0.0f;
    float d0 = ovy[0] * scale;
    float d1 = ovy[1] * scale;
    float d2 = ovy[2] * scale;
    if (s == 0) { v[0] = d0; v[1] = d1; v[2] = d2; }
    else        { v[1] = d0; v[2] = d1; v[3] = d2; }
    need1 = (v[2] != 0.0f) || (v[3] != 0.0f);
    return a;
}

// ---------------------------------------------------------------------------
// Kernel 1: scatter pin density into the bin map. (unchanged from R12/R13 —
// measured win, do not touch.)
// ---------------------------------------------------------------------------
__global__ void __launch_bounds__(256) k_scatter(const float* __restrict__ pos,
                                                 const float* __restrict__ nsx,
                                                 const float* __restrict__ nsy,
                                                 const int*   __restrict__ pin_start) {
    int i = blockIdx.x * blockDim.x + threadIdx.x;
    if (i >= NUM_PHYS) return;

    float sx = nsx[i];
    float sy = nsy[i];
    float hx = 0.5f * fmaxf(stretch_c(), sx);
    float hy = 0.5f * fmaxf(stretch_c(), sy);
    float cx = pos[i]             + 0.5f * sx;
    float cy = pos[NUM_NODES + i] + 0.5f * sy;

    float pw = (float)(pin_start[i + 1] - pin_start[i]);
    float density = pw / (4.0f * hx * hy);

    int   ix[KSTEN], iy[KSTEN];
    float ovx[KSTEN], ovy[KSTEN];
    overlap_terms(cx - hx, cx + hx, ix, ovx);
    overlap_terms(cy - hy, cy + hy, iy, ovy);

    float v[4];
    bool need_p1;
    int a = pack_y(iy, ovy, density, v, need_p1);
    bool fuse4 = need_p1 && ((a & 3) == 0);       // 16B-aligned window

#pragma unroll
    for (int kx = 0; kx < KSTEN; kx++) {
        float r = ovx[kx];
        if (r == 0.0f) continue;                  // skip zero x-rows
        float* rowp = &g_pin_map[ix[kx] * NB + a];
        if (fuse4) {
            red_add_v4(rowp, r * v[0], r * v[1], r * v[2], r * v[3]);
        } else {
            red_add_v2(rowp, r * v[0], r * v[1]);
            if (need_p1)
                red_add_v2(rowp + 2, r * v[2], r * v[3]);
        }
    }
}

// ---------------------------------------------------------------------------
// Kernel 2: util = clip(pin_map / (BSX*BSY*cap), 1/1.5, 1.5), float4-wide,
//           + re-zero pin_map for the next graph replay.
// ---------------------------------------------------------------------------
__global__ void __launch_bounds__(256) k_util() {
    int i = blockIdx.x * blockDim.x + threadIdx.x;
    if (i >= (NB * NB) / 4) return;
    float4 p = ((const float4*)g_pin_map)[i];
    float4 u;
    u.x = fminf(fmaxf(p.x / cap_denom(), min_rate()), 1.5f);
    u.y = fminf(fmaxf(p.y / cap_denom(), min_rate()), 1.5f);
    u.z = fminf(fmaxf(p.z / cap_denom(), min_rate()), 1.5f);
    u.w = fminf(fmaxf(p.w / cap_denom(), min_rate()), 1.5f);
    ((float4*)g_util)[i] = u;
    ((float4*)g_pin_map)[i] = make_float4(0.0f, 0.0f, 0.0f, 0.0f);
}

// ---------------------------------------------------------------------------
// Kernel 3: gather, TWO nodes per thread.
//  - float2 vector loads of pos/nsx/nsy (m even, NUM_NODES even -> aligned)
//  - two independent accumulator chains interleaved per kx row: doubles the
//    outstanding-load MLP per warp slot (gather is L2-latency bound)
//  - per-node arithmetic order identical to R13 (bit-for-bit)
// NUM_MOVABLE is even, so every thread owns a full pair.
// ---------------------------------------------------------------------------
__global__ void __launch_bounds__(256) k_gather(const float* __restrict__ pos,
                                                const float* __restrict__ nsx,
                                                const float* __restrict__ nsy,
                                                float* __restrict__ out) {
    int t = blockIdx.x * blockDim.x + threadIdx.x;
    int m = 2 * t;
    if (m >= NUM_MOVABLE) return;

    float2 xl = *(const float2*)&pos[m];
    float2 yl = *(const float2*)&pos[NUM_NODES + m];
    float2 sx = *(const float2*)&nsx[m];
    float2 sy = *(const float2*)&nsy[m];

    // Node A stencil
    int   jxA[KSTEN], jyA[KSTEN];
    float wxA[KSTEN], wyA[KSTEN];
    overlap_terms(xl.x, xl.x + sx.x, jxA, wxA);
    overlap_terms(yl.x, yl.x + sy.x, jyA, wyA);
    float vA[4]; bool p1A;
    int aA = pack_y(jyA, wyA, 1.0f, vA, p1A);

    // Node B stencil
    int   jxB[KSTEN], jyB[KSTEN];
    float wxB[KSTEN], wyB[KSTEN];
    overlap_terms(xl.y, xl.y + sx.y, jxB, wxB);
    overlap_terms(yl.y, yl.y + sy.y, jyB, wyB);
    float vB[4]; bool p1B;
    int aB = pack_y(jyB, wyB, 1.0f, vB, p1B);

    float accA = 0.0f, accB = 0.0f;
#pragma unroll
    for (int kx = 0; kx < KSTEN; kx++) {
        float wa = wxA[kx];
        if (wa != 0.0f) {
            const float* rowp = &g_util[jxA[kx] * NB + aA];
            float2 u0 = *(const float2*)rowp;
            accA += wa * (vA[0] * u0.x + vA[1] * u0.y);
            if (p1A) {
                float2 u1 = *(const float2*)(rowp + 2);
                accA += wa * (vA[2] * u1.x + vA[3] * u1.y);
            }
        }
        float wb = wxB[kx];
        if (wb != 0.0f) {
            const float* rowp = &g_util[jxB[kx] * NB + aB];
            float2 u0 = *(const float2*)rowp;
            accB += wb * (vB[0] * u0.x + vB[1] * u0.y);
            if (p1B) {
                float2 u1 = *(const float2*)(rowp + 2);
                accB += wb * (vB[2] * u1.x + vB[3] * u1.y);
            }
        }
    }
    *(float2*)&out[m] = make_float2(accA, accB);
}

// ---------------------------------------------------------------------------
extern "C" void kernel_launch(void* const* d_in, const int* in_sizes, int n_in,
                              void* d_out, int out_size) {
    const float* pos       = (const float*)d_in[0];   // 2*NUM_NODES
    const float* nsx       = (const float*)d_in[1];   // NUM_NODES
    const float* nsy       = (const float*)d_in[2];   // NUM_NODES
    const int*   pin_start = (const int*)  d_in[3];   // NUM_PHYS+1
    float*       out       = (float*)d_out;           // NUM_MOVABLE

    k_scatter<<<(NUM_PHYS + 255) / 256, 256>>>(pos, nsx, nsy, pin_start);
    k_util<<<((NB * NB) / 4 + 255) / 256, 256>>>();
    k_gather<<<(NUM_MOVABLE / 2 + 255) / 256, 256>>>(pos, nsx, nsy, out);
}